// round 3
// baseline (speedup 1.0000x reference)
#include <cuda_runtime.h>
#include <cuda_bf16.h>
#include <math.h>
#include <stdint.h>

// ---------------- scratch (static __device__, no allocs) ----------------
__device__ unsigned int g_adj[512];          // adjacency bitmask: row d, bit s
__device__ float g_P[128 * 512];
__device__ float g_Q[128 * 512];
__device__ float g_h1[128 * 512];
__device__ float g_h2[128 * 512];
__device__ float g_partial[128 * 512];
__device__ float g_v0[512];
__device__ __nv_bfloat16 g_w2t_hi[2][512 * 512];   // W2^T split: [n][k]
__device__ __nv_bfloat16 g_w2t_lo[2][512 * 512];

// ---------------- adjacency ----------------
__global__ void zero_adj_kernel() { g_adj[threadIdx.x] = 0u; }   // 512 threads

__global__ void build_adj_kernel(const int* __restrict__ ei, int E) {
    __shared__ unsigned int s_adj[512];
    for (int i = threadIdx.x; i < 512; i += blockDim.x) s_adj[i] = 0u;
    __syncthreads();
    int stride = gridDim.x * blockDim.x;
    for (int e = blockIdx.x * blockDim.x + threadIdx.x; e < E; e += stride) {
        int s = ei[e];        // src
        int d = ei[E + e];    // dst
        atomicOr(&s_adj[(d << 2) + (s >> 5)], 1u << (s & 31));
    }
    __syncthreads();
    for (int i = threadIdx.x; i < 512; i += blockDim.x) {
        unsigned int w = s_adj[i];
        if (w) atomicOr(&g_adj[i], w);
    }
}

// ---------------- P/Q mini-GEMMs ----------------
__global__ void pq_kernel(const float* __restrict__ x_ext,
                          const float* __restrict__ W1,
                          const float* __restrict__ b1,
                          int C, int use_h1) {
    __shared__ float xs[512];
    const float* xin = use_h1 ? g_h1 : x_ext;
    int d = blockIdx.x, h = threadIdx.x;
    if (h < C) xs[h] = xin[d * C + h];
    __syncthreads();
    float p = b1[h], q = 0.f;
    for (int k = 0; k < C; k++) {
        float xv = xs[k];
        float wt = W1[k * 512 + h];
        float wb = W1[(C + k) * 512 + h];
        p = fmaf(xv, wt - wb, p);
        q = fmaf(xv, wb, q);
    }
    g_P[d * 512 + h] = p;
    g_Q[d * 512 + h] = q;
}

// ---------------- W2 transpose + bf16 split ----------------
__global__ void prep_w2_kernel(const float* __restrict__ W2, int layer) {
    int n = blockIdx.x;
    __nv_bfloat16* ph = g_w2t_hi[layer];
    __nv_bfloat16* pl = g_w2t_lo[layer];
    for (int k = threadIdx.x; k < 512; k += blockDim.x) {
        float v = W2[k * 512 + n];
        __nv_bfloat16 h = __float2bfloat16(v);
        ph[n * 512 + k] = h;
        pl[n * 512 + k] = __float2bfloat16(v - __bfloat162float(h));
    }
}

// ---------------- mma.sync helpers ----------------
static __device__ __forceinline__ void mma16816(float* c, const uint32_t* a,
                                                uint32_t b0, uint32_t b1) {
    asm("mma.sync.aligned.m16n8k16.row.col.f32.bf16.bf16.f32 "
        "{%0,%1,%2,%3}, {%4,%5,%6,%7}, {%8,%9}, {%0,%1,%2,%3};"
        : "+f"(c[0]), "+f"(c[1]), "+f"(c[2]), "+f"(c[3])
        : "r"(a[0]), "r"(a[1]), "r"(a[2]), "r"(a[3]), "r"(b0), "r"(b1));
}
static __device__ __forceinline__ uint32_t bf16x2_pack(float hi, float lo) {
    uint32_t r;
    asm("cvt.rn.bf16x2.f32 %0, %1, %2;" : "=r"(r) : "f"(hi), "f"(lo));
    return r;
}

// ---------------- tensor-core pair-GEMM + masked segment-max ----------------
// One CTA per d (128 CTAs, 1 wave). out[d,n] = relu( max_{s in adj[d]}
//   (relu(P[d]+Q[s]) @ W2)[s,n] + b2[n] )
// bf16 3-term split via mma.sync.m16n8k16; accumulators in registers.
// 8 warps tile 128(s) x 256(n) per n-half; BK=32; register prefetch pipeline.
#define KW   18     // padded row width in u32 (16 data + 2 pad)
#define OFF_PS   0
#define OFF_AH   2048
#define OFF_AL   (OFF_AH + 128 * KW * 4)        // 2048 + 9216  = 11264
#define OFF_BH   (OFF_AL + 128 * KW * 4)        // 11264 + 9216 = 20480
#define OFF_BL   (OFF_BH + 256 * KW * 4)        // 20480 + 18432 = 38912
#define OFF_RED  OFF_BH                          // reuse B region post-loop
#define GM_SMEM  (OFF_BL + 256 * KW * 4)        // 57344

__global__ __launch_bounds__(256) void gemm_mma_kernel(int layer,
                                                       const float* __restrict__ b2,
                                                       int outSel) {
    extern __shared__ char smem[];
    float*    Ps  = (float*)(smem + OFF_PS);
    uint32_t* AsH = (uint32_t*)(smem + OFF_AH);
    uint32_t* AsL = (uint32_t*)(smem + OFF_AL);
    uint32_t* BsH = (uint32_t*)(smem + OFF_BH);
    uint32_t* BsL = (uint32_t*)(smem + OFF_BL);
    float*    red = (float*)(smem + OFF_RED);

    int t = threadIdx.x, d = blockIdx.x;
    int wid = t >> 5, lane = t & 31;
    int g = lane >> 2, tq = lane & 3;
    int wm = (wid & 3) * 32;        // warp row base (s)
    int wn = (wid >> 2) * 128;      // warp col base within 256-wide half

    Ps[t]       = g_P[d * 512 + t];
    Ps[t + 256] = g_P[d * 512 + t + 256];

    unsigned am = g_adj[d * 4 + (wid & 3)];
    bool ok0 = (am >> (g))      & 1u;
    bool ok1 = (am >> (g + 8))  & 1u;
    bool ok2 = (am >> (g + 16)) & 1u;
    bool ok3 = (am >> (g + 24)) & 1u;

    int sA = t >> 1, hA = t & 1;    // A staging: row sA (0..127), col-half hA

    const uint32_t* WH = (const uint32_t*)g_w2t_hi[layer];
    const uint32_t* WL = (const uint32_t*)g_w2t_lo[layer];
    float* outp = outSel ? g_h2 : g_h1;
    __syncthreads();

    for (int nh = 0; nh < 2; nh++) {
        float c[2][16][4];
        #pragma unroll
        for (int mf = 0; mf < 2; mf++)
            #pragma unroll
            for (int nf = 0; nf < 16; nf++)
                #pragma unroll
                for (int i = 0; i < 4; i++) c[mf][nf][i] = 0.f;

        // prefetch iter 0
        uint32_t stBh[16], stBl[16];
        float4 stQ[4];
        {
            const uint32_t* sh = WH + (size_t)(nh * 256 + t) * 256;
            const uint32_t* sl = WL + (size_t)(nh * 256 + t) * 256;
            #pragma unroll
            for (int j = 0; j < 16; j++) { stBh[j] = sh[j]; stBl[j] = sl[j]; }
            const float4* q = (const float4*)(g_Q + sA * 512 + hA * 16);
            #pragma unroll
            for (int j = 0; j < 4; j++) stQ[j] = q[j];
        }

        for (int it = 0; it < 16; it++) {
            int k0 = it * 32;
            __syncthreads();           // prior iter's MMA consumed smem
            // ---- store staged B tiles
            #pragma unroll
            for (int j = 0; j < 16; j++) {
                BsH[t * KW + j] = stBh[j];
                BsL[t * KW + j] = stBl[j];
            }
            // ---- build A tile: relu(P+Q) split into hi/lo bf16
            #pragma unroll
            for (int j = 0; j < 4; j++) {
                float4 q = stQ[j];
                int kb = k0 + hA * 16 + j * 4;
                float a0 = fmaxf(Ps[kb + 0] + q.x, 0.f);
                float a1 = fmaxf(Ps[kb + 1] + q.y, 0.f);
                float a2 = fmaxf(Ps[kb + 2] + q.z, 0.f);
                float a3 = fmaxf(Ps[kb + 3] + q.w, 0.f);
                uint32_t h01 = bf16x2_pack(a1, a0);
                uint32_t h23 = bf16x2_pack(a3, a2);
                float f0 = __uint_as_float(h01 << 16);
                float f1 = __uint_as_float(h01 & 0xffff0000u);
                float f2 = __uint_as_float(h23 << 16);
                float f3 = __uint_as_float(h23 & 0xffff0000u);
                uint32_t l01 = bf16x2_pack(a1 - f1, a0 - f0);
                uint32_t l23 = bf16x2_pack(a3 - f3, a2 - f2);
                int col = hA * 8 + j * 2;
                AsH[sA * KW + col]     = h01;
                AsH[sA * KW + col + 1] = h23;
                AsL[sA * KW + col]     = l01;
                AsL[sA * KW + col + 1] = l23;
            }
            __syncthreads();
            // ---- prefetch next iter (regs only; latency hidden under MMA)
            if (it < 15) {
                int k1 = k0 + 32;
                const uint32_t* sh = WH + (size_t)(nh * 256 + t) * 256 + (k1 >> 1);
                const uint32_t* sl = WL + (size_t)(nh * 256 + t) * 256 + (k1 >> 1);
                #pragma unroll
                for (int j = 0; j < 16; j++) { stBh[j] = sh[j]; stBl[j] = sl[j]; }
                const float4* q = (const float4*)(g_Q + sA * 512 + k1 + hA * 16);
                #pragma unroll
                for (int j = 0; j < 4; j++) stQ[j] = q[j];
            }
            // ---- A fragments
            uint32_t aH[2][2][4], aL[2][2][4];
            #pragma unroll
            for (int mf = 0; mf < 2; mf++) {
                int rb = wm + mf * 16;
                #pragma unroll
                for (int kf = 0; kf < 2; kf++) {
                    int cb = kf * 8 + tq;
                    aH[mf][kf][0] = AsH[(rb + g) * KW + cb];
                    aH[mf][kf][1] = AsH[(rb + g + 8) * KW + cb];
                    aH[mf][kf][2] = AsH[(rb + g) * KW + cb + 4];
                    aH[mf][kf][3] = AsH[(rb + g + 8) * KW + cb + 4];
                    aL[mf][kf][0] = AsL[(rb + g) * KW + cb];
                    aL[mf][kf][1] = AsL[(rb + g + 8) * KW + cb];
                    aL[mf][kf][2] = AsL[(rb + g) * KW + cb + 4];
                    aL[mf][kf][3] = AsL[(rb + g + 8) * KW + cb + 4];
                }
            }
            // ---- MMAs: 16 n-frags x 2 m x 2 k x 3 terms
            #pragma unroll
            for (int nf = 0; nf < 16; nf++) {
                int nr = (wn + nf * 8 + g) * KW;
                #pragma unroll
                for (int kf = 0; kf < 2; kf++) {
                    int cb = kf * 8 + tq;
                    uint32_t bh0 = BsH[nr + cb], bh1 = BsH[nr + cb + 4];
                    uint32_t bl0 = BsL[nr + cb], bl1 = BsL[nr + cb + 4];
                    #pragma unroll
                    for (int mf = 0; mf < 2; mf++) {
                        mma16816(c[mf][nf], aH[mf][kf], bh0, bh1);
                        mma16816(c[mf][nf], aH[mf][kf], bl0, bl1);
                        mma16816(c[mf][nf], aL[mf][kf], bh0, bh1);
                    }
                }
            }
        }

        // ---- epilogue: masked segment-max over s
        __syncthreads();   // all warps done reading B region before red reuse
        #pragma unroll
        for (int nf = 0; nf < 16; nf++) {
            float v0 = -INFINITY, v1 = -INFINITY;
            if (ok0) { v0 = fmaxf(v0, c[0][nf][0]); v1 = fmaxf(v1, c[0][nf][1]); }
            if (ok1) { v0 = fmaxf(v0, c[0][nf][2]); v1 = fmaxf(v1, c[0][nf][3]); }
            if (ok2) { v0 = fmaxf(v0, c[1][nf][0]); v1 = fmaxf(v1, c[1][nf][1]); }
            if (ok3) { v0 = fmaxf(v0, c[1][nf][2]); v1 = fmaxf(v1, c[1][nf][3]); }
            #pragma unroll
            for (int off = 4; off < 32; off <<= 1) {
                v0 = fmaxf(v0, __shfl_xor_sync(0xffffffffu, v0, off));
                v1 = fmaxf(v1, __shfl_xor_sync(0xffffffffu, v1, off));
            }
            if (g == 0) {
                int col = wn + nf * 8 + 2 * tq;
                red[(wid & 3) * 256 + col]     = v0;
                red[(wid & 3) * 256 + col + 1] = v1;
            }
        }
        __syncthreads();
        {
            float m = fmaxf(fmaxf(red[t], red[256 + t]),
                            fmaxf(red[512 + t], red[768 + t]));
            outp[d * 512 + nh * 256 + t] = fmaxf(m + b2[nh * 256 + t], 0.f);
        }
    }
}

// ---------------- dense head ----------------
__global__ void dense_partial_kernel(const float* __restrict__ linW) {
    __shared__ float vs[512];
    int kb = blockIdx.x, t = threadIdx.x;   // 512 threads
    vs[t] = g_h2[kb * 512 + t];
    __syncthreads();
    float acc = 0.f;
    const float* W = linW + (size_t)kb * 512 * 512;
    #pragma unroll 4
    for (int k = 0; k < 512; k++)
        acc = fmaf(vs[k], W[(size_t)k * 512 + t], acc);
    g_partial[kb * 512 + t] = acc;
}

__global__ void dense_reduce_kernel(const float* __restrict__ lin_b) {
    int t = threadIdx.x;   // 512
    float s = 0.f;
    #pragma unroll 8
    for (int b = 0; b < 128; b++) s += g_partial[b * 512 + t];
    g_v0[t] = fmaxf(s + lin_b[t], 0.f);
}

__global__ void head_kernel(const float* __restrict__ lin1W, const float* __restrict__ lin1b,
                            const float* __restrict__ outW, const float* __restrict__ outb,
                            float* __restrict__ out) {
    __shared__ float v0s[512];
    __shared__ float v1s[256];
    __shared__ float lg[128];
    __shared__ float es[128];
    int t = threadIdx.x;   // 256
    v0s[t]       = g_v0[t];
    v0s[t + 256] = g_v0[t + 256];
    __syncthreads();
    float a = lin1b[t];
    for (int k = 0; k < 512; k++) a = fmaf(v0s[k], lin1W[k * 256 + t], a);
    v1s[t] = fmaxf(a, 0.f);
    __syncthreads();
    if (t < 128) {
        float a2 = outb[t];
        for (int k = 0; k < 256; k++) a2 = fmaf(v1s[k], outW[k * 128 + t], a2);
        lg[t] = fmaxf(a2, 0.f);
    }
    __syncthreads();
    if (t < 128) {
        float mx = -INFINITY;
        for (int i = 0; i < 128; i++) mx = fmaxf(mx, lg[i]);
        es[t] = expf(lg[t] - mx);
    }
    __syncthreads();
    if (t < 128) {
        float sm = 0.f;
        for (int i = 0; i < 128; i++) sm += es[i];
        out[t] = es[t] / sm;
    }
}

// ---------------- launch ----------------
extern "C" void kernel_launch(void* const* d_in, const int* in_sizes, int n_in,
                              void* d_out, int out_size) {
    const float* x     = (const float*)d_in[0];
    const int*   ei    = (const int*)d_in[1];
    const float* c1W1  = (const float*)d_in[2];
    const float* c1b1  = (const float*)d_in[3];
    const float* c1W2  = (const float*)d_in[4];
    const float* c1b2  = (const float*)d_in[5];
    const float* c2W1  = (const float*)d_in[6];
    const float* c2b1  = (const float*)d_in[7];
    const float* c2W2  = (const float*)d_in[8];
    const float* c2b2  = (const float*)d_in[9];
    const float* linW  = (const float*)d_in[10];
    const float* linb  = (const float*)d_in[11];
    const float* lin1W = (const float*)d_in[12];
    const float* lin1b = (const float*)d_in[13];
    const float* outW  = (const float*)d_in[14];
    const float* outb  = (const float*)d_in[15];
    float* out = (float*)d_out;
    int E = in_sizes[1] / 2;

    cudaFuncSetAttribute(gemm_mma_kernel, cudaFuncAttributeMaxDynamicSharedMemorySize, GM_SMEM);

    zero_adj_kernel<<<1, 512>>>();
    build_adj_kernel<<<128, 256>>>(ei, E);
    prep_w2_kernel<<<512, 256>>>(c1W2, 0);
    prep_w2_kernel<<<512, 256>>>(c2W2, 1);

    // EdgeConv 1 (C = 256)
    pq_kernel<<<128, 512>>>(x, c1W1, c1b1, 256, 0);
    gemm_mma_kernel<<<128, 256, GM_SMEM>>>(0, c1b2, 0);

    // EdgeConv 2 (C = 512)
    pq_kernel<<<128, 512>>>(nullptr, c2W1, c2b1, 512, 1);
    gemm_mma_kernel<<<128, 256, GM_SMEM>>>(1, c2b2, 1);

    // dense head
    dense_partial_kernel<<<128, 512>>>(linW);
    dense_reduce_kernel<<<1, 512>>>(linb);
    head_kernel<<<1, 256>>>(lin1W, lin1b, outW, outb, out);
}

// round 5
// speedup vs baseline: 1.5497x; 1.5497x over previous
#include <cuda_runtime.h>
#include <cuda_bf16.h>
#include <math.h>
#include <stdint.h>

// ---------------- scratch (static __device__, no allocs) ----------------
__device__ unsigned int g_adj[512];          // adjacency bitmask: row d, bit s
__device__ float g_P[128 * 512];
__device__ float g_Q[128 * 512];
__device__ float g_h1[128 * 512];
__device__ float g_h2[128 * 512];
__device__ float g_partial[128 * 512];
__device__ float g_v0[512];
__device__ __nv_bfloat16 g_w2t_hi[2][512 * 512];   // W2^T split: [n][k]
__device__ __nv_bfloat16 g_w2t_lo[2][512 * 512];

// ---------------- adjacency ----------------
__global__ void zero_adj_kernel() { g_adj[threadIdx.x] = 0u; }   // 512 threads

__global__ void build_adj_kernel(const int* __restrict__ ei, int E) {
    __shared__ unsigned int s_adj[512];
    for (int i = threadIdx.x; i < 512; i += blockDim.x) s_adj[i] = 0u;
    __syncthreads();
    int stride = gridDim.x * blockDim.x;
    for (int e = blockIdx.x * blockDim.x + threadIdx.x; e < E; e += stride) {
        int s = ei[e];        // src
        int d = ei[E + e];    // dst
        atomicOr(&s_adj[(d << 2) + (s >> 5)], 1u << (s & 31));
    }
    __syncthreads();
    for (int i = threadIdx.x; i < 512; i += blockDim.x) {
        unsigned int w = s_adj[i];
        if (w) atomicOr(&g_adj[i], w);
    }
}

// ---------------- P/Q mini-GEMMs ----------------
__global__ void pq_kernel(const float* __restrict__ x_ext,
                          const float* __restrict__ W1,
                          const float* __restrict__ b1,
                          int C, int use_h1) {
    __shared__ float xs[512];
    const float* xin = use_h1 ? g_h1 : x_ext;
    int d = blockIdx.x, h = threadIdx.x;
    if (h < C) xs[h] = xin[d * C + h];
    __syncthreads();
    float p = b1[h], q = 0.f;
    #pragma unroll 8
    for (int k = 0; k < C; k++) {
        float xv = xs[k];
        float wt = W1[k * 512 + h];
        float wb = W1[(C + k) * 512 + h];
        p = fmaf(xv, wt - wb, p);
        q = fmaf(xv, wb, q);
    }
    g_P[d * 512 + h] = p;
    g_Q[d * 512 + h] = q;
}

// ---------------- W2 transpose + bf16 split (both layers fused) ----------------
__global__ void prep_w2_kernel(const float* __restrict__ W2a,
                               const float* __restrict__ W2b) {
    int n = blockIdx.x, layer = blockIdx.y;
    const float* W2 = layer ? W2b : W2a;
    __nv_bfloat16* ph = g_w2t_hi[layer];
    __nv_bfloat16* pl = g_w2t_lo[layer];
    for (int k = threadIdx.x; k < 512; k += blockDim.x) {
        float v = W2[k * 512 + n];
        __nv_bfloat16 h = __float2bfloat16(v);
        ph[n * 512 + k] = h;
        pl[n * 512 + k] = __float2bfloat16(v - __bfloat162float(h));
    }
}

// ---------------- mma helpers ----------------
static __device__ __forceinline__ void mma16816(float* c, const uint32_t* a,
                                                uint32_t b0, uint32_t b1) {
    asm("mma.sync.aligned.m16n8k16.row.col.f32.bf16.bf16.f32 "
        "{%0,%1,%2,%3}, {%4,%5,%6,%7}, {%8,%9}, {%0,%1,%2,%3};"
        : "+f"(c[0]), "+f"(c[1]), "+f"(c[2]), "+f"(c[3])
        : "r"(a[0]), "r"(a[1]), "r"(a[2]), "r"(a[3]), "r"(b0), "r"(b1));
}
static __device__ __forceinline__ uint32_t bf16x2_pack(float hi, float lo) {
    uint32_t r;
    asm("cvt.rn.bf16x2.f32 %0, %1, %2;" : "=r"(r) : "f"(hi), "f"(lo));
    return r;
}
static __device__ __forceinline__ uint32_t smem_u32(const void* p) {
    uint32_t a;
    asm("{ .reg .u64 t; cvta.to.shared.u64 t, %1; cvt.u32.u64 %0, t; }" : "=r"(a) : "l"(p));
    return a;
}
static __device__ __forceinline__ void cp16(uint32_t dst, const void* src) {
    asm volatile("cp.async.cg.shared.global [%0], [%1], 16;" :: "r"(dst), "l"(src) : "memory");
}

// ---------------- tensor-core pair-GEMM + masked segment-max ----------------
// One CTA per d (128 CTAs, 1 wave).
// out[d,n] = relu( max_{s in adj[d]} (relu(P[d]+Q[s]) @ W2)[s,n] + b2[n] )
// 3-term bf16 split via mma.sync.m16n8k16. 4 n-passes of BN=128; BK=32,
// double-buffered smem. RACE FIX vs R4: cp.async issue + A-build for the next
// buffer are ordered AFTER the per-iter __syncthreads, so no warp can
// overwrite a buffer another warp is still MMA-reading.
#define KW 20                                   // u32 per row (16 data + 4 pad)
#define OFF_PS   0
#define OFF_ADJ  2048
#define OFF_A    2176                           // [2 dbuf][hi,lo] each 128*20*4 = 10240B
#define OFF_B    (OFF_A + 40960)                // 43136
#define GM_SMEM  (OFF_B + 40960)                // 84096

__global__ __launch_bounds__(256, 1) void gemm_mma_kernel(int layer,
                                                          const float* __restrict__ b2,
                                                          int outSel) {
    extern __shared__ char smem[];
    float* Ps = (float*)(smem + OFF_PS);
    unsigned* adjw = (unsigned*)(smem + OFF_ADJ);
    uint32_t sb_B = smem_u32(smem) + OFF_B;

    int t = threadIdx.x, d = blockIdx.x;
    int wid = t >> 5, lane = t & 31;
    int g = lane >> 2, tq = lane & 3;
    int wm = (wid & 3) * 32;        // warp s-base
    int wnl = (wid >> 2) * 64;      // warp n-base within 128-wide pass

    Ps[t]       = g_P[d * 512 + t];
    Ps[t + 256] = g_P[d * 512 + t + 256];
    if (t < 4) adjw[t] = g_adj[d * 4 + t];
    __syncthreads();

    unsigned am = adjw[wid & 3];
    bool ok[4];
    ok[0] = (am >> (g)) & 1u;
    ok[1] = (am >> (g + 8)) & 1u;
    ok[2] = (am >> (g + 16)) & 1u;
    ok[3] = (am >> (g + 24)) & 1u;

    int sA = t >> 1, hA = t & 1;    // A build: row sA, k-half hA
    int rB = t >> 1, segB = t & 1;  // B copy: row rB, 2x16B segs

    const char* WHbase = (const char*)g_w2t_hi[layer];
    const char* WLbase = (const char*)g_w2t_lo[layer];
    float* outp = outSel ? g_h2 : g_h1;

    for (int nh = 0; nh < 4; nh++) {
        __syncthreads();   // red region (A buf0) reads finished; safe to rebuild

        float c[2][8][4];
        #pragma unroll
        for (int mf = 0; mf < 2; mf++)
            #pragma unroll
            for (int nf = 0; nf < 8; nf++)
                #pragma unroll
                for (int i = 0; i < 4; i++) c[mf][nf][i] = 0.f;

        const char* WHrow = WHbase + (size_t)(nh * 128 + rB) * 1024;
        const char* WLrow = WLbase + (size_t)(nh * 128 + rB) * 1024;

        // ---- prologue: issue B tile 0 + build A tile 0 (buf 0)
        {
            uint32_t dh = sb_B + rB * 80 + segB * 32;
            uint32_t dl = dh + 10240;
            cp16(dh, WHrow + segB * 32);
            cp16(dh + 16, WHrow + segB * 32 + 16);
            cp16(dl, WLrow + segB * 32);
            cp16(dl + 16, WLrow + segB * 32 + 16);
            asm volatile("cp.async.commit_group;" ::: "memory");
        }
        {
            uint32_t* AH = (uint32_t*)(smem + OFF_A);
            uint32_t* AL = AH + 2560;
            const float4* q4 = (const float4*)(g_Q + sA * 512 + hA * 16);
            #pragma unroll
            for (int j = 0; j < 4; j++) {
                float4 q = q4[j];
                int kb = hA * 16 + j * 4;
                float a0 = fmaxf(Ps[kb + 0] + q.x, 0.f);
                float a1 = fmaxf(Ps[kb + 1] + q.y, 0.f);
                float a2 = fmaxf(Ps[kb + 2] + q.z, 0.f);
                float a3 = fmaxf(Ps[kb + 3] + q.w, 0.f);
                uint32_t h01 = bf16x2_pack(a1, a0);
                uint32_t h23 = bf16x2_pack(a3, a2);
                float f0 = __uint_as_float(h01 << 16);
                float f1 = __uint_as_float(h01 & 0xffff0000u);
                float f2 = __uint_as_float(h23 << 16);
                float f3 = __uint_as_float(h23 & 0xffff0000u);
                int col = sA * KW + hA * 8 + j * 2;
                AH[col]     = h01;
                AH[col + 1] = h23;
                AL[col]     = bf16x2_pack(a1 - f1, a0 - f0);
                AL[col + 1] = bf16x2_pack(a3 - f3, a2 - f2);
            }
        }

        for (int it = 0; it < 16; it++) {
            int buf = it & 1, nbuf = buf ^ 1;

            asm volatile("cp.async.wait_group 0;" ::: "memory");  // B[it] landed
            __syncthreads();  // A[it]/B[it] visible to all; all MMA reads of nbuf done

            if (it < 15) {
                // ---- issue B[it+1] into nbuf (safe: after barrier)
                uint32_t dh = sb_B + nbuf * 20480 + rB * 80 + segB * 32;
                uint32_t dl = dh + 10240;
                const char* sh = WHrow + (it + 1) * 64 + segB * 32;
                const char* sl = WLrow + (it + 1) * 64 + segB * 32;
                cp16(dh, sh);          cp16(dh + 16, sh + 16);
                cp16(dl, sl);          cp16(dl + 16, sl + 16);
                asm volatile("cp.async.commit_group;" ::: "memory");

                // ---- build A[it+1] into nbuf
                uint32_t* AH = (uint32_t*)(smem + OFF_A + nbuf * 20480);
                uint32_t* AL = AH + 2560;
                int k1 = (it + 1) * 32;
                const float4* q4 = (const float4*)(g_Q + sA * 512 + k1 + hA * 16);
                #pragma unroll
                for (int j = 0; j < 4; j++) {
                    float4 q = q4[j];
                    int kb = k1 + hA * 16 + j * 4;
                    float a0 = fmaxf(Ps[kb + 0] + q.x, 0.f);
                    float a1 = fmaxf(Ps[kb + 1] + q.y, 0.f);
                    float a2 = fmaxf(Ps[kb + 2] + q.z, 0.f);
                    float a3 = fmaxf(Ps[kb + 3] + q.w, 0.f);
                    uint32_t h01 = bf16x2_pack(a1, a0);
                    uint32_t h23 = bf16x2_pack(a3, a2);
                    float f0 = __uint_as_float(h01 << 16);
                    float f1 = __uint_as_float(h01 & 0xffff0000u);
                    float f2 = __uint_as_float(h23 << 16);
                    float f3 = __uint_as_float(h23 & 0xffff0000u);
                    int col = sA * KW + hA * 8 + j * 2;
                    AH[col]     = h01;
                    AH[col + 1] = h23;
                    AL[col]     = bf16x2_pack(a1 - f1, a0 - f0);
                    AL[col + 1] = bf16x2_pack(a3 - f3, a2 - f2);
                }
            }

            // ---- MMAs on buf
            uint32_t* AH = (uint32_t*)(smem + OFF_A + buf * 20480);
            uint32_t* AL = AH + 2560;
            uint32_t* BH = (uint32_t*)(smem + OFF_B + buf * 20480);
            uint32_t* BL = BH + 2560;

            uint32_t aH[2][2][4], aL[2][2][4];
            #pragma unroll
            for (int mf = 0; mf < 2; mf++) {
                int rb = wm + mf * 16;
                #pragma unroll
                for (int kf = 0; kf < 2; kf++) {
                    int cb = kf * 8 + tq;
                    aH[mf][kf][0] = AH[(rb + g) * KW + cb];
                    aH[mf][kf][1] = AH[(rb + g + 8) * KW + cb];
                    aH[mf][kf][2] = AH[(rb + g) * KW + cb + 4];
                    aH[mf][kf][3] = AH[(rb + g + 8) * KW + cb + 4];
                    aL[mf][kf][0] = AL[(rb + g) * KW + cb];
                    aL[mf][kf][1] = AL[(rb + g + 8) * KW + cb];
                    aL[mf][kf][2] = AL[(rb + g) * KW + cb + 4];
                    aL[mf][kf][3] = AL[(rb + g + 8) * KW + cb + 4];
                }
            }
            #pragma unroll
            for (int nf = 0; nf < 8; nf++) {
                int nr = (wnl + nf * 8 + g) * KW;
                #pragma unroll
                for (int kf = 0; kf < 2; kf++) {
                    int cb = kf * 8 + tq;
                    uint32_t bh0 = BH[nr + cb], bh1 = BH[nr + cb + 4];
                    uint32_t bl0 = BL[nr + cb], bl1 = BL[nr + cb + 4];
                    #pragma unroll
                    for (int mf = 0; mf < 2; mf++) {
                        mma16816(c[mf][nf], aH[mf][kf], bh0, bh1);
                        mma16816(c[mf][nf], aH[mf][kf], bl0, bl1);
                        mma16816(c[mf][nf], aL[mf][kf], bh0, bh1);
                    }
                }
            }
        }

        // ---- epilogue: masked segment-max over s
        __syncthreads();
        float* red = (float*)(smem + OFF_A);   // 4 x 128 floats
        #pragma unroll
        for (int nf = 0; nf < 8; nf++) {
            float v0 = -INFINITY, v1 = -INFINITY;
            if (ok[0]) { v0 = fmaxf(v0, c[0][nf][0]); v1 = fmaxf(v1, c[0][nf][1]); }
            if (ok[1]) { v0 = fmaxf(v0, c[0][nf][2]); v1 = fmaxf(v1, c[0][nf][3]); }
            if (ok[2]) { v0 = fmaxf(v0, c[1][nf][0]); v1 = fmaxf(v1, c[1][nf][1]); }
            if (ok[3]) { v0 = fmaxf(v0, c[1][nf][2]); v1 = fmaxf(v1, c[1][nf][3]); }
            #pragma unroll
            for (int off = 4; off < 32; off <<= 1) {
                v0 = fmaxf(v0, __shfl_xor_sync(0xffffffffu, v0, off));
                v1 = fmaxf(v1, __shfl_xor_sync(0xffffffffu, v1, off));
            }
            if (g == 0) {
                int col = wnl + nf * 8 + 2 * tq;
                red[(wid & 3) * 128 + col]     = v0;
                red[(wid & 3) * 128 + col + 1] = v1;
            }
        }
        __syncthreads();
        if (t < 128) {
            float m = fmaxf(fmaxf(red[t], red[128 + t]),
                            fmaxf(red[256 + t], red[384 + t]));
            outp[d * 512 + nh * 128 + t] = fmaxf(m + b2[nh * 128 + t], 0.f);
        }
    }
}

// ---------------- dense head ----------------
__global__ void dense_partial_kernel(const float* __restrict__ linW) {
    __shared__ float vs[512];
    int kb = blockIdx.x, t = threadIdx.x;   // 512 threads
    vs[t] = g_h2[kb * 512 + t];
    __syncthreads();
    float acc0 = 0.f, acc1 = 0.f;
    const float* W = linW + (size_t)kb * 512 * 512;
    #pragma unroll 8
    for (int k = 0; k < 512; k += 2) {
        acc0 = fmaf(vs[k],     W[(size_t)k * 512 + t],       acc0);
        acc1 = fmaf(vs[k + 1], W[(size_t)(k + 1) * 512 + t], acc1);
    }
    g_partial[kb * 512 + t] = acc0 + acc1;
}

__global__ void dense_reduce_kernel(const float* __restrict__ lin_b) {
    int t = threadIdx.x;   // 512
    float s = 0.f;
    #pragma unroll 8
    for (int b = 0; b < 128; b++) s += g_partial[b * 512 + t];
    g_v0[t] = fmaxf(s + lin_b[t], 0.f);
}

__global__ void head_kernel(const float* __restrict__ lin1W, const float* __restrict__ lin1b,
                            const float* __restrict__ outW, const float* __restrict__ outb,
                            float* __restrict__ out) {
    __shared__ float v0s[512];
    __shared__ float v1s[256];
    __shared__ float lg[128];
    __shared__ float es[128];
    int t = threadIdx.x;   // 256
    v0s[t]       = g_v0[t];
    v0s[t + 256] = g_v0[t + 256];
    __syncthreads();
    float a = lin1b[t];
    #pragma unroll 8
    for (int k = 0; k < 512; k++) a = fmaf(v0s[k], lin1W[k * 256 + t], a);
    v1s[t] = fmaxf(a, 0.f);
    __syncthreads();
    if (t < 128) {
        float a2 = outb[t];
        #pragma unroll 8
        for (int k = 0; k < 256; k++) a2 = fmaf(v1s[k], outW[k * 128 + t], a2);
        lg[t] = fmaxf(a2, 0.f);
    }
    __syncthreads();
    if (t < 128) {
        float mx = -INFINITY;
        for (int i = 0; i < 128; i++) mx = fmaxf(mx, lg[i]);
        es[t] = expf(lg[t] - mx);
    }
    __syncthreads();
    if (t < 128) {
        float sm = 0.f;
        for (int i = 0; i < 128; i++) sm += es[i];
        out[t] = es[t] / sm;
    }
}

// ---------------- launch ----------------
extern "C" void kernel_launch(void* const* d_in, const int* in_sizes, int n_in,
                              void* d_out, int out_size) {
    const float* x     = (const float*)d_in[0];
    const int*   ei    = (const int*)d_in[1];
    const float* c1W1  = (const float*)d_in[2];
    const float* c1b1  = (const float*)d_in[3];
    const float* c1W2  = (const float*)d_in[4];
    const float* c1b2  = (const float*)d_in[5];
    const float* c2W1  = (const float*)d_in[6];
    const float* c2b1  = (const float*)d_in[7];
    const float* c2W2  = (const float*)d_in[8];
    const float* c2b2  = (const float*)d_in[9];
    const float* linW  = (const float*)d_in[10];
    const float* linb  = (const float*)d_in[11];
    const float* lin1W = (const float*)d_in[12];
    const float* lin1b = (const float*)d_in[13];
    const float* outW  = (const float*)d_in[14];
    const float* outb  = (const float*)d_in[15];
    float* out = (float*)d_out;
    int E = in_sizes[1] / 2;

    cudaFuncSetAttribute(gemm_mma_kernel, cudaFuncAttributeMaxDynamicSharedMemorySize, GM_SMEM);

    zero_adj_kernel<<<1, 512>>>();
    build_adj_kernel<<<128, 256>>>(ei, E);
    prep_w2_kernel<<<dim3(512, 2), 256>>>(c1W2, c2W2);

    // EdgeConv 1 (C = 256)
    pq_kernel<<<128, 512>>>(x, c1W1, c1b1, 256, 0);
    gemm_mma_kernel<<<128, 256, GM_SMEM>>>(0, c1b2, 0);

    // EdgeConv 2 (C = 512)
    pq_kernel<<<128, 512>>>(nullptr, c2W1, c2b1, 512, 1);
    gemm_mma_kernel<<<128, 256, GM_SMEM>>>(1, c2b2, 1);

    // dense head
    dense_partial_kernel<<<128, 512>>>(linW);
    dense_reduce_kernel<<<1, 512>>>(linb);
    head_kernel<<<1, 256>>>(lin1W, lin1b, outW, outb, out);
}